// round 12
// baseline (speedup 1.0000x reference)
#include <cuda_runtime.h>
#include <cuda_bf16.h>
#include <cstdint>
#include <cfloat>

#define NSAMP   50000
#define DIMS    3072
#define BROWS   128
#define NCLS    10
#define KC      128           // K elements per smem chunk (128 int8 = 128B = SW128 row)
#define NKC     24            // 3072 / 128
#define TILEN   128           // samples per CTA tile
#define NTILES  391           // ceil(50000/128)
#define DSTRIDE 50048         // 391*128, row stride of d2 matrix
#define MARGIN  25.0f         // covers worst int8 quantization d2 error (~9) twice over
#define NTHREADS 384          // 256 consumer + 128 producer

#define QSCALE   21.166666f   // 127/6
#define INV_S2   (1.0f / (QSCALE * QSCALE))

// ---------------- device scratch (static globals; no allocation) ----------------
__device__ float g_x2[BROWS];
__device__ __align__(16) signed char g_xa[NKC * 16384];   // X int8, SW128-swizzled 16KB chunks
__device__ float g_d2[(size_t)BROWS * DSTRIDE];           // approx d2, 25.6 MB

// ---------------- helpers ----------------
__device__ __forceinline__ unsigned smem_u32(const void* p) {
    unsigned a;
    asm("{ .reg .u64 t; cvta.to.shared.u64 t, %1; cvt.u32.u64 %0, t; }" : "=r"(a) : "l"(p));
    return a;
}
__device__ __forceinline__ unsigned sw128(unsigned off) { return off ^ ((off >> 3) & 0x70); }
__device__ __forceinline__ unsigned long long umin64(unsigned long long a, unsigned long long b) {
    return a < b ? a : b;
}

__device__ __forceinline__ void ldsm_x4(unsigned r[4], unsigned addr) {
    asm volatile("ldmatrix.sync.aligned.m8n8.x4.shared.b16 {%0,%1,%2,%3}, [%4];"
                 : "=r"(r[0]), "=r"(r[1]), "=r"(r[2]), "=r"(r[3]) : "r"(addr));
}
__device__ __forceinline__ void ldsm_x2(unsigned r[2], unsigned addr) {
    asm volatile("ldmatrix.sync.aligned.m8n8.x2.shared.b16 {%0,%1}, [%2];"
                 : "=r"(r[0]), "=r"(r[1]) : "r"(addr));
}
__device__ __forceinline__ void mma_s8(int c[4], const unsigned a[4], const unsigned b[2]) {
    asm volatile(
        "mma.sync.aligned.m16n8k32.row.col.s32.s8.s8.s32 "
        "{%0,%1,%2,%3}, {%4,%5,%6,%7}, {%8,%9}, {%0,%1,%2,%3};"
        : "+r"(c[0]), "+r"(c[1]), "+r"(c[2]), "+r"(c[3])
        : "r"(a[0]), "r"(a[1]), "r"(a[2]), "r"(a[3]), "r"(b[0]), "r"(b[1]));
}
// pack 4 s32 -> 4 saturated s8 bytes (little-endian i0..i3)
__device__ __forceinline__ unsigned pack_s8x4(int i0, int i1, int i2, int i3) {
    unsigned t, r;
    asm("cvt.pack.sat.s8.s32.b32 %0, %1, %2, %3;" : "=r"(t) : "r"(i3), "r"(i2), "r"(0));
    asm("cvt.pack.sat.s8.s32.b32 %0, %1, %2, %3;" : "=r"(r) : "r"(i1), "r"(i0), "r"(t));
    return r;
}
__device__ __forceinline__ unsigned quant4(float4 v) {
    return pack_s8x4(__float2int_rn(v.x * QSCALE), __float2int_rn(v.y * QSCALE),
                     __float2int_rn(v.z * QSCALE), __float2int_rn(v.w * QSCALE));
}
__device__ __forceinline__ void cp_async16(unsigned saddr, const void* gptr) {
    asm volatile("cp.async.ca.shared.global [%0], [%1], 16;" :: "r"(saddr), "l"(gptr) : "memory");
}
__device__ __forceinline__ void cp_async_wait_all() {
    asm volatile("cp.async.wait_all;" ::: "memory");
}
__device__ __forceinline__ void bar_sync(int id) {
    asm volatile("bar.sync %0, %1;" :: "r"(id), "r"(NTHREADS) : "memory");
}
__device__ __forceinline__ void bar_arrive(int id) {
    asm volatile("bar.arrive %0, %1;" :: "r"(id), "r"(NTHREADS) : "memory");
}

// ---------------- kernel 1: X -> int8 swizzled chunks + ||x||^2 ----------------
__global__ void __launch_bounds__(256) prep_kernel(const float* __restrict__ x) {
    const int m = blockIdx.x, tid = threadIdx.x;
    float acc = 0.f;
    for (int k = tid; k < DIMS; k += 256) {
        float v = x[m * DIMS + k];
        acc += v * v;
        int kc = k >> 7, col = k & 127;
        int q = __float2int_rn(v * QSCALE);
        q = q > 127 ? 127 : (q < -127 ? -127 : q);
        g_xa[kc * 16384 + sw128((unsigned)(m * 128 + col))] = (signed char)q;
    }
    #pragma unroll
    for (int o = 16; o; o >>= 1) acc += __shfl_down_sync(0xffffffffu, acc, o);
    __shared__ float part[8];
    if ((tid & 31) == 0) part[tid >> 5] = acc;
    __syncthreads();
    if (tid == 0) {
        float t = 0.f;
        #pragma unroll
        for (int i = 0; i < 8; i++) t += part[i];
        g_x2[m] = t;
    }
}

// ---------------- kernel 2: warp-specialized int8 distance GEMM ----------------
// Warps 0-7: consumers (ldmatrix + IMMA + epilogue). Warps 8-11: producers
// (LDG samples fp32 -> s8 quantize -> STS, cp.async A chunk, exact s2).
// Named barriers: EMPTY[p]=2+p (consumers arrive, producers sync),
//                 FULL[p] =4+p (producers arrive, consumers sync).
__global__ void __launch_bounds__(NTHREADS) pass1_kernel(const float* __restrict__ samples) {
    extern __shared__ __align__(16) unsigned char dynsm[];
    __shared__ float s2[TILEN];

    const int tid = threadIdx.x, lane = tid & 31, wid = tid >> 5;
    const int n0 = blockIdx.x * TILEN;

    const unsigned dynbase = smem_u32(dynsm);
    const unsigned pad = ((dynbase + 1023u) & ~1023u) - dynbase;
    unsigned char* pA = dynsm + pad;                     // A bufs: pA + p*16384
    unsigned char* pB = pA + 32768;                      // B bufs: pB + p*16384
    const unsigned aA = dynbase + pad;
    const unsigned aB = aA + 32768;

    if (wid < 8) {
        // ================= CONSUMERS =================
        const int wm = wid >> 2, wn = wid & 3;           // warp tile: 64(M) x 32(N)
        // ldmatrix byte geometry (int8, 128B rows): tile row + 16B column select
        const int a_row  = (lane & 7) + ((lane >> 3) & 1) * 8;
        const int a_kb   = (lane >> 4) * 16;             // byte offset within k32 step
        const int b_row  = (lane & 7);
        const int b_kb   = (((lane & 15) >> 3)) * 16;

        int c[4][4][4];
        #pragma unroll
        for (int mt = 0; mt < 4; mt++)
            #pragma unroll
            for (int nt = 0; nt < 4; nt++)
                #pragma unroll
                for (int r = 0; r < 4; r++) c[mt][nt][r] = 0;

        for (int kc = 0; kc < NKC; kc++) {
            const int p = kc & 1;
            bar_sync(4 + p);                             // wait FULL[p]
            const unsigned bA = aA + p * 16384, bB = aB + p * 16384;
            #pragma unroll
            for (int ks = 0; ks < 4; ks++) {             // 4 k-steps of k32
                unsigned a[4][4], b[4][2];
                #pragma unroll
                for (int mt = 0; mt < 4; mt++) {
                    int row = wm * 64 + mt * 16 + a_row;
                    ldsm_x4(a[mt], bA + sw128((unsigned)(row * 128 + ks * 32 + a_kb)));
                }
                #pragma unroll
                for (int nt = 0; nt < 4; nt++) {
                    int row = wn * 32 + nt * 8 + b_row;
                    ldsm_x2(b[nt], bB + sw128((unsigned)(row * 128 + ks * 32 + b_kb)));
                }
                #pragma unroll
                for (int mt = 0; mt < 4; mt++)
                    #pragma unroll
                    for (int nt = 0; nt < 4; nt++)
                        mma_s8(c[mt][nt], a[mt], b[nt]);
            }
            bar_arrive(2 + p);                           // signal EMPTY[p]
        }

        __syncthreads();                                 // producers published s2

        // epilogue: d2 = x2 + s2 - 2*invS2*dot_int, float2-coalesced
        const int g = lane >> 2, cq = lane & 3;
        #pragma unroll
        for (int mt = 0; mt < 4; mt++) {
            int r0 = wm * 64 + mt * 16 + g;
            float x2a = g_x2[r0], x2b = g_x2[r0 + 8];
            #pragma unroll
            for (int nt = 0; nt < 4; nt++) {
                int col = wn * 32 + nt * 8 + 2 * cq;
                int ng = n0 + col;
                float s2a = s2[col], s2b = s2[col + 1];
                const float k2 = 2.0f * INV_S2;
                float2 v0, v1;
                v0.x = fmaxf(x2a + s2a - k2 * (float)c[mt][nt][0], 0.f);
                v0.y = fmaxf(x2a + s2b - k2 * (float)c[mt][nt][1], 0.f);
                v1.x = fmaxf(x2b + s2a - k2 * (float)c[mt][nt][2], 0.f);
                v1.y = fmaxf(x2b + s2b - k2 * (float)c[mt][nt][3], 0.f);
                *(float2*)&g_d2[(size_t)r0 * DSTRIDE + ng] = v0;
                *(float2*)&g_d2[(size_t)(r0 + 8) * DSTRIDE + ng] = v1;
            }
        }
    } else {
        // ================= PRODUCERS =================
        const int ptid = tid - 256;                      // 0..127
        const int q = ptid & 15, rbase = ptid >> 4;      // 16 float4 per 64-elem half-row
        const float* tb = samples + (size_t)(n0 + rbase) * DIMS + q * 4;

        float s2p[16];
        #pragma unroll
        for (int j = 0; j < 16; j++) s2p[j] = 0.f;

        float4 vb[16];

        for (int kc = 0; kc < NKC; kc++) {
            const int p = kc & 1;
            const int kb = kc * KC;
            unsigned char* dB = pB + p * 16384;

            // half 0 loads issued BEFORE waiting: latency hides under consumer MMA
            #pragma unroll
            for (int j = 0; j < 16; j++) {
                int n = n0 + rbase + 8 * j;
                vb[j] = (n < NSAMP) ? *(const float4*)(tb + (size_t)(8 * j) * DIMS + kb)
                                    : make_float4(0.f, 0.f, 0.f, 0.f);
            }

            if (kc >= 2) bar_sync(2 + p);                // wait EMPTY[p]

            // A chunk via cp.async (L2-hot)
            {
                unsigned dstA = aA + p * 16384 + ptid * 16;
                const unsigned char* srcA = (const unsigned char*)g_xa + kc * 16384 + ptid * 16;
                #pragma unroll
                for (int i = 0; i < 8; i++)
                    cp_async16(dstA + i * 2048, srcA + i * 2048);
            }

            // half 0: quantize + swizzled STS (4B words), accumulate exact s2
            #pragma unroll
            for (int j = 0; j < 16; j++) {
                float4 v = vb[j];
                s2p[j] = fmaf(v.x, v.x, fmaf(v.y, v.y, fmaf(v.z, v.z, fmaf(v.w, v.w, s2p[j]))));
                *(unsigned*)(dB + sw128((unsigned)((rbase + 8 * j) * 128 + q * 4))) = quant4(v);
            }
            // half 1: load + quantize + STS
            #pragma unroll
            for (int j = 0; j < 16; j++) {
                int n = n0 + rbase + 8 * j;
                vb[j] = (n < NSAMP) ? *(const float4*)(tb + (size_t)(8 * j) * DIMS + kb + 64)
                                    : make_float4(0.f, 0.f, 0.f, 0.f);
            }
            #pragma unroll
            for (int j = 0; j < 16; j++) {
                float4 v = vb[j];
                s2p[j] = fmaf(v.x, v.x, fmaf(v.y, v.y, fmaf(v.z, v.z, fmaf(v.w, v.w, s2p[j]))));
                *(unsigned*)(dB + sw128((unsigned)((rbase + 8 * j) * 128 + 64 + q * 4))) = quant4(v);
            }

            cp_async_wait_all();
            __threadfence_block();
            bar_arrive(4 + p);                           // signal FULL[p]
        }

        // s2 reduction: 16 threads (same rbase) share each row
        #pragma unroll
        for (int j = 0; j < 16; j++) {
            float v = s2p[j];
            #pragma unroll
            for (int o = 8; o; o >>= 1) v += __shfl_down_sync(0xffffffffu, v, o, 16);
            if ((lane & 15) == 0) s2[rbase + 8 * j] = v;
        }
        __syncthreads();                                 // matches consumers'
    }
}

// ---------------- kernel 3: per-row min + candidate exact rescore + outputs ----------------
__global__ void __launch_bounds__(256) pass2_kernel(const float* __restrict__ x,
                                                    const float* __restrict__ samples,
                                                    const void* __restrict__ cls,
                                                    float* __restrict__ out) {
    __shared__ unsigned long long wred[8];
    __shared__ unsigned long long s_best;
    __shared__ float fred[8];
    __shared__ int s_cand[2048];
    __shared__ int s_cnt;

    const int m = blockIdx.x, tid = threadIdx.x, lane = tid & 31, wid = tid >> 5;
    const float* drow = &g_d2[(size_t)m * DSTRIDE];

    // 1) approx min with packed (d2,idx) key -> jnp argmin tie-break (smallest idx)
    unsigned long long best = ~0ull;
    for (int i = tid; i < NSAMP; i += 256) {
        float d = drow[i];
        best = umin64(best, ((unsigned long long)__float_as_uint(d) << 32) | (unsigned)i);
    }
    #pragma unroll
    for (int o = 16; o; o >>= 1) best = umin64(best, __shfl_down_sync(0xffffffffu, best, o));
    if (lane == 0) wred[wid] = best;
    if (tid == 0) s_cnt = 0;
    __syncthreads();
    if (tid == 0) {
        unsigned long long b = wred[0];
        #pragma unroll
        for (int i = 1; i < 8; i++) b = umin64(b, wred[i]);
        s_best = b;
    }
    __syncthreads();

    // 2) collect candidates within margin of approx min
    const float thresh = __uint_as_float((unsigned)(s_best >> 32)) + MARGIN;
    for (int i = tid; i < NSAMP; i += 256) {
        if (drow[i] <= thresh) {
            int p = atomicAdd(&s_cnt, 1);
            if (p < 2048) s_cand[p] = i;
        }
    }
    __syncthreads();
    const int cnt = s_cnt < 2048 ? s_cnt : 2048;

    // 3) exact fp32 rescore of candidates
    unsigned long long ebest = ~0ull;   // only thread 0's value is meaningful
    const float* xr = x + (size_t)m * DIMS;
    for (int ci = 0; ci < cnt; ci++) {
        int idx = s_cand[ci];
        const float* sr = samples + (size_t)idx * DIMS;
        float acc = 0.f;
        for (int j = tid; j < DIMS; j += 256) {
            float dx = xr[j] - sr[j];
            acc = fmaf(dx, dx, acc);
        }
        #pragma unroll
        for (int o = 16; o; o >>= 1) acc += __shfl_down_sync(0xffffffffu, acc, o);
        if (lane == 0) fred[wid] = acc;
        __syncthreads();
        if (tid == 0) {
            float t = 0.f;
            #pragma unroll
            for (int i = 0; i < 8; i++) t += fred[i];
            ebest = umin64(ebest, ((unsigned long long)__float_as_uint(fmaxf(t, 0.f)) << 32)
                                  | (unsigned)idx);
        }
        __syncthreads();
    }
    if (tid == 0) s_best = ebest;
    __syncthreads();

    const unsigned bidx = (unsigned)(s_best & 0xffffffffu);
    const float d2e = __uint_as_float((unsigned)(s_best >> 32));

    // imgs: out[1280 .. 1280 + 128*3072)
    const float4* src = (const float4*)(samples + (size_t)bidx * DIMS);
    float4* dst = (float4*)(out + BROWS * NCLS + (size_t)m * DIMS);
    #pragma unroll
    for (int i = 0; i < 3; i++) dst[tid + i * 256] = src[tid + i * 256];

    if (tid == 0) {
        out[BROWS * NCLS + BROWS * DIMS + m] = sqrtf(d2e);     // l2s
        // classes dtype detection: int64 little-endian => odd int32 words all zero
        const unsigned* ci = (const unsigned*)cls;
        int nz = 0;
        for (int j = 1; j < 256; j += 2) nz += (ci[j] != 0u) ? 1 : 0;
        int cv;
        if (nz == 0) cv = (int)((const long long*)cls)[bidx];
        else         cv = ((const int*)cls)[bidx];
        #pragma unroll
        for (int j = 0; j < NCLS; j++) out[m * NCLS + j] = (j == cv) ? 1.0f : 0.0f;
    }
}

// ---------------- launcher ----------------
extern "C" void kernel_launch(void* const* d_in, const int* in_sizes, int n_in,
                              void* d_out, int out_size) {
    (void)in_sizes; (void)n_in; (void)out_size;
    const float* x       = (const float*)d_in[0];
    const float* samples = (const float*)d_in[1];
    const void*  cls     = d_in[2];
    float*       out     = (float*)d_out;

    cudaFuncSetAttribute(pass1_kernel, cudaFuncAttributeMaxDynamicSharedMemorySize, 66560);
    prep_kernel<<<BROWS, 256>>>(x);
    pass1_kernel<<<NTILES, NTHREADS, 66560>>>(samples);
    pass2_kernel<<<BROWS, 256>>>(x, samples, cls, out);
}

// round 14
// speedup vs baseline: 2.1762x; 2.1762x over previous
#include <cuda_runtime.h>
#include <cuda_bf16.h>
#include <cstdint>
#include <cfloat>

#define NSAMP   50000
#define DIMS    3072
#define BROWS   128
#define NCLS    10
#define KC      64            // K elements per smem chunk (64 bf16 = 128B = SW128 row)
#define NKC     48            // 3072 / 64
#define NT4TILES 296          // 296 tiles of N=128 -> 2 perfect waves
#define NT4BASE  37888        // 296*128
#define NT3TILES 127          // ceil((50000-37888)/96) tail tiles of N=96
#define NGRID    (NT4TILES + NT3TILES)
#define DSTRIDE 50080         // row stride of d2 matrix (>= 37888+127*96 = 50080)
#define MARGIN  8.0f          // >5x worst-case bf16 d2 error bound
#define NTHREADS 384          // 256 consumer + 128 producer

// ---------------- device scratch (static globals; no allocation) ----------------
__device__ unsigned long long g_best[BROWS];                  // packed (d2bits<<32)|idx
__device__ float g_x2[BROWS];
__device__ __align__(16) __nv_bfloat16 g_xb[NKC * 8192];      // X bf16, SW128-swizzled 16KB chunks
__device__ float g_d2[(size_t)BROWS * DSTRIDE];               // approx d2, 25.6 MB

// ---------------- helpers ----------------
__device__ __forceinline__ unsigned smem_u32(const void* p) {
    unsigned a;
    asm("{ .reg .u64 t; cvta.to.shared.u64 t, %1; cvt.u32.u64 %0, t; }" : "=r"(a) : "l"(p));
    return a;
}
__device__ __forceinline__ unsigned sw128(unsigned off) { return off ^ ((off >> 3) & 0x70); }
__device__ __forceinline__ unsigned long long umin64(unsigned long long a, unsigned long long b) {
    return a < b ? a : b;
}

__device__ __forceinline__ void ldsm_x4(unsigned r[4], unsigned addr) {
    asm volatile("ldmatrix.sync.aligned.m8n8.x4.shared.b16 {%0,%1,%2,%3}, [%4];"
                 : "=r"(r[0]), "=r"(r[1]), "=r"(r[2]), "=r"(r[3]) : "r"(addr));
}
__device__ __forceinline__ void ldsm_x2(unsigned r[2], unsigned addr) {
    asm volatile("ldmatrix.sync.aligned.m8n8.x2.shared.b16 {%0,%1}, [%2];"
                 : "=r"(r[0]), "=r"(r[1]) : "r"(addr));
}
__device__ __forceinline__ void mma_bf16(float c[4], const unsigned a[4], const unsigned b[2]) {
    asm volatile(
        "mma.sync.aligned.m16n8k16.row.col.f32.bf16.bf16.f32 "
        "{%0,%1,%2,%3}, {%4,%5,%6,%7}, {%8,%9}, {%0,%1,%2,%3};"
        : "+f"(c[0]), "+f"(c[1]), "+f"(c[2]), "+f"(c[3])
        : "r"(a[0]), "r"(a[1]), "r"(a[2]), "r"(a[3]), "r"(b[0]), "r"(b[1]));
}
__device__ __forceinline__ unsigned pack_bf16x2(float hi, float lo) {
    unsigned r;
    asm("cvt.rn.bf16x2.f32 %0, %1, %2;" : "=r"(r) : "f"(hi), "f"(lo));
    return r;
}
__device__ __forceinline__ void cp_async16(unsigned saddr, const void* gptr) {
    asm volatile("cp.async.ca.shared.global [%0], [%1], 16;" :: "r"(saddr), "l"(gptr) : "memory");
}
__device__ __forceinline__ void cp_async_wait_all() {
    asm volatile("cp.async.wait_all;" ::: "memory");
}
__device__ __forceinline__ void bar_sync(int id) {
    asm volatile("bar.sync %0, %1;" :: "r"(id), "r"(NTHREADS) : "memory");
}
__device__ __forceinline__ void bar_arrive(int id) {
    asm volatile("bar.arrive %0, %1;" :: "r"(id), "r"(NTHREADS) : "memory");
}

// ---------------- kernel 1: X -> bf16 swizzled chunks + ||x||^2 ----------------
// 384 blocks: 3 per row, 1024 elems each. g_x2 pre-zeroed by memset.
__global__ void __launch_bounds__(256) prep_kernel(const float* __restrict__ x) {
    const int b = blockIdx.x, tid = threadIdx.x;
    const int m = b / 3, seg = b % 3;
    float acc = 0.f;
    #pragma unroll
    for (int i = 0; i < 4; i++) {
        int k = seg * 1024 + tid + i * 256;
        float v = x[m * DIMS + k];
        acc += v * v;
        int kc = k >> 6, col = k & 63;
        unsigned sw = sw128((unsigned)(m * 128 + col * 2)) >> 1;   // element index
        g_xb[kc * 8192 + sw] = __float2bfloat16(v);
    }
    #pragma unroll
    for (int o = 16; o; o >>= 1) acc += __shfl_down_sync(0xffffffffu, acc, o);
    __shared__ float part[8];
    if ((tid & 31) == 0) part[tid >> 5] = acc;
    __syncthreads();
    if (tid == 0) {
        float t = 0.f;
        #pragma unroll
        for (int i = 0; i < 8; i++) t += part[i];
        atomicAdd(&g_x2[m], t);
    }
}

// ---------------- pass1 body: warp-specialized bf16 distance GEMM ----------------
// NT = n8 subtiles per consumer warp (4 -> tile N=128, 3 -> tile N=96).
// Each of 8 producer row-bases covers 4*NT rows (TILEN = 32*NT = 8 bases * 4NT).
// Warps 0-7: consumers (ldsm + HMMA + epilogue w/ fused per-row min).
// Warps 8-11: producers (LDG fp32 -> bf16 -> STS, cp.async A chunk, exact s2).
template <int NT>
__device__ __forceinline__ void pass1_body(const float* __restrict__ samples, int n0,
                                           unsigned char* pA, unsigned char* pB,
                                           unsigned aA, unsigned aB, float* s2) {
    const int tid = threadIdx.x, lane = tid & 31, wid = tid >> 5;

    if (wid < 8) {
        // ================= CONSUMERS =================
        const int wm = wid >> 2, wn = wid & 3;           // warp tile: 64(M) x NT*8(N)
        const int a_row  = (lane & 7) + ((lane >> 3) & 1) * 8;
        const int a_koff = (lane >> 4) * 8;
        const int b_row  = (lane & 7);
        const int b_koff = (((lane & 15) >> 3)) * 8;

        float c[4][NT][4];
        #pragma unroll
        for (int mt = 0; mt < 4; mt++)
            #pragma unroll
            for (int nt = 0; nt < NT; nt++)
                #pragma unroll
                for (int r = 0; r < 4; r++) c[mt][nt][r] = 0.f;

        for (int kc = 0; kc < NKC; kc++) {
            const int p = kc & 1;
            bar_sync(4 + p);                             // wait FULL[p]
            const unsigned bA = aA + p * 16384, bB = aB + p * 16384;
            #pragma unroll
            for (int ks = 0; ks < 4; ks++) {
                unsigned a[4][4], b[NT][2];
                #pragma unroll
                for (int mt = 0; mt < 4; mt++) {
                    int row = wm * 64 + mt * 16 + a_row;
                    int ke  = ks * 16 + a_koff;
                    ldsm_x4(a[mt], bA + sw128((unsigned)(row * 128 + ke * 2)));
                }
                #pragma unroll
                for (int nt = 0; nt < NT; nt++) {
                    int row = wn * (NT * 8) + nt * 8 + b_row;
                    int ke  = ks * 16 + b_koff;
                    ldsm_x2(b[nt], bB + sw128((unsigned)(row * 128 + ke * 2)));
                }
                #pragma unroll
                for (int mt = 0; mt < 4; mt++)
                    #pragma unroll
                    for (int nt = 0; nt < NT; nt++)
                        mma_bf16(c[mt][nt], a[mt], b[nt]);
            }
            bar_arrive(2 + p);                           // signal EMPTY[p]
        }

        __syncthreads();                                 // producers published s2

        // epilogue: d2 write + fused per-row (d2,idx) min -> g_best
        const int g = lane >> 2, cq = lane & 3;
        #pragma unroll
        for (int mt = 0; mt < 4; mt++) {
            int r0 = wm * 64 + mt * 16 + g;
            float x2a = g_x2[r0], x2b = g_x2[r0 + 8];
            unsigned long long klo = ~0ull, khi = ~0ull;
            #pragma unroll
            for (int nt = 0; nt < NT; nt++) {
                int col = wn * (NT * 8) + nt * 8 + 2 * cq;
                int ng = n0 + col;
                float s2a = s2[col], s2b = s2[col + 1];
                float2 v0, v1;
                v0.x = fmaxf(x2a + s2a - 2.f * c[mt][nt][0], 0.f);
                v0.y = fmaxf(x2a + s2b - 2.f * c[mt][nt][1], 0.f);
                v1.x = fmaxf(x2b + s2a - 2.f * c[mt][nt][2], 0.f);
                v1.y = fmaxf(x2b + s2b - 2.f * c[mt][nt][3], 0.f);
                *(float2*)&g_d2[(size_t)r0 * DSTRIDE + ng] = v0;
                *(float2*)&g_d2[(size_t)(r0 + 8) * DSTRIDE + ng] = v1;
                if (ng < NSAMP) {
                    klo = umin64(klo, ((unsigned long long)__float_as_uint(v0.x) << 32) | (unsigned)ng);
                    khi = umin64(khi, ((unsigned long long)__float_as_uint(v1.x) << 32) | (unsigned)ng);
                }
                if (ng + 1 < NSAMP) {
                    klo = umin64(klo, ((unsigned long long)__float_as_uint(v0.y) << 32) | (unsigned)(ng + 1));
                    khi = umin64(khi, ((unsigned long long)__float_as_uint(v1.y) << 32) | (unsigned)(ng + 1));
                }
            }
            // reduce across the 4 lanes sharing this row (lane = 4g+cq)
            #pragma unroll
            for (int o = 2; o; o >>= 1) {
                klo = umin64(klo, __shfl_down_sync(0xffffffffu, klo, o, 4));
                khi = umin64(khi, __shfl_down_sync(0xffffffffu, khi, o, 4));
            }
            if (cq == 0) {
                atomicMin(&g_best[r0], klo);
                atomicMin(&g_best[r0 + 8], khi);
            }
        }
    } else {
        // ================= PRODUCERS =================
        const int ptid = tid - 256;                      // 0..127
        const int q = ptid & 15, rbase = ptid >> 4;      // col-quarter, row base
        const float* tb = samples + (size_t)(n0 + rbase) * DIMS + q * 4;

        float s2p[4 * NT];
        #pragma unroll
        for (int j = 0; j < 4 * NT; j++) s2p[j] = 0.f;

        float4 vb[4 * NT];

        for (int kc = 0; kc < NKC; kc++) {
            const int p = kc & 1;
            const int kb = kc * KC;

            // issue B loads BEFORE waiting: DRAM latency hides under consumer MMA
            #pragma unroll
            for (int j = 0; j < 4 * NT; j++) {
                int n = n0 + rbase + 8 * j;
                vb[j] = (n < NSAMP) ? *(const float4*)(tb + (size_t)(8 * j) * DIMS + kb)
                                    : make_float4(0.f, 0.f, 0.f, 0.f);
            }

            if (kc >= 2) bar_sync(2 + p);                // wait EMPTY[p]

            // A chunk via cp.async (L2-hot)
            {
                unsigned dstA = aA + p * 16384 + ptid * 16;
                const unsigned char* srcA = (const unsigned char*)g_xb + kc * 16384 + ptid * 16;
                #pragma unroll
                for (int i = 0; i < 8; i++)
                    cp_async16(dstA + i * 2048, srcA + i * 2048);
            }

            // convert B to bf16 + swizzled STS, accumulate exact s2
            unsigned char* dB = pB + p * 16384;
            #pragma unroll
            for (int j = 0; j < 4 * NT; j++) {
                float4 v = vb[j];
                s2p[j] = fmaf(v.x, v.x, fmaf(v.y, v.y, fmaf(v.z, v.z, fmaf(v.w, v.w, s2p[j]))));
                uint2 H;
                H.x = pack_bf16x2(v.y, v.x);
                H.y = pack_bf16x2(v.w, v.z);
                *(uint2*)(dB + sw128((unsigned)((rbase + 8 * j) * 128 + q * 8))) = H;
            }

            cp_async_wait_all();
            __threadfence_block();
            bar_arrive(4 + p);                           // signal FULL[p]
        }

        // s2 reduction: 16 threads (same rbase) share each row
        #pragma unroll
        for (int j = 0; j < 4 * NT; j++) {
            float v = s2p[j];
            #pragma unroll
            for (int o = 8; o; o >>= 1) v += __shfl_down_sync(0xffffffffu, v, o, 16);
            if ((lane & 15) == 0) s2[rbase + 8 * j] = v;
        }
        __syncthreads();                                 // matches consumers'
    }
}

__global__ void __launch_bounds__(NTHREADS) pass1_kernel(const float* __restrict__ samples) {
    extern __shared__ __align__(16) unsigned char dynsm[];
    __shared__ float s2[128];

    const unsigned dynbase = smem_u32(dynsm);
    const unsigned pad = ((dynbase + 1023u) & ~1023u) - dynbase;
    unsigned char* pA = dynsm + pad;                     // A bufs: pA + p*16384
    unsigned char* pB = pA + 32768;                      // B bufs: pB + p*16384
    const unsigned aA = dynbase + pad;
    const unsigned aB = aA + 32768;

    const int bid = blockIdx.x;
    if (bid < NT4TILES) {
        pass1_body<4>(samples, bid * 128, pA, pB, aA, aB, s2);
    } else {
        pass1_body<3>(samples, NT4BASE + (bid - NT4TILES) * 96, pA, pB, aA, aB, s2);
    }
}

// ---------------- kernel 3: candidate scan + exact rescore + outputs ----------------
__global__ void __launch_bounds__(256) pass2_kernel(const float* __restrict__ x,
                                                    const float* __restrict__ samples,
                                                    const void* __restrict__ cls,
                                                    float* __restrict__ out) {
    __shared__ unsigned long long s_best;
    __shared__ float fred[8];
    __shared__ int s_cand[2048];
    __shared__ int s_cnt;

    const int m = blockIdx.x, tid = threadIdx.x, lane = tid & 31, wid = tid >> 5;
    const float* drow = &g_d2[(size_t)m * DSTRIDE];

    if (tid == 0) s_cnt = 0;
    __syncthreads();

    // global approx min was fused into pass1 (g_best)
    const float thresh = __uint_as_float((unsigned)(g_best[m] >> 32)) + MARGIN;
    for (int i = tid; i < NSAMP; i += 256) {
        if (drow[i] <= thresh) {
            int p = atomicAdd(&s_cnt, 1);
            if (p < 2048) s_cand[p] = i;
        }
    }
    __syncthreads();
    const int cnt = s_cnt < 2048 ? s_cnt : 2048;

    // exact fp32 rescore of candidates
    unsigned long long ebest = ~0ull;   // only thread 0's value is meaningful
    const float* xr = x + (size_t)m * DIMS;
    for (int ci = 0; ci < cnt; ci++) {
        int idx = s_cand[ci];
        const float* sr = samples + (size_t)idx * DIMS;
        float acc = 0.f;
        for (int j = tid; j < DIMS; j += 256) {
            float dx = xr[j] - sr[j];
            acc = fmaf(dx, dx, acc);
        }
        #pragma unroll
        for (int o = 16; o; o >>= 1) acc += __shfl_down_sync(0xffffffffu, acc, o);
        if (lane == 0) fred[wid] = acc;
        __syncthreads();
        if (tid == 0) {
            float t = 0.f;
            #pragma unroll
            for (int i = 0; i < 8; i++) t += fred[i];
            ebest = umin64(ebest, ((unsigned long long)__float_as_uint(fmaxf(t, 0.f)) << 32)
                                  | (unsigned)idx);
        }
        __syncthreads();
    }
    if (tid == 0) s_best = ebest;
    __syncthreads();

    const unsigned bidx = (unsigned)(s_best & 0xffffffffu);
    const float d2e = __uint_as_float((unsigned)(s_best >> 32));

    // imgs: out[1280 .. 1280 + 128*3072)
    const float4* src = (const float4*)(samples + (size_t)bidx * DIMS);
    float4* dst = (float4*)(out + BROWS * NCLS + (size_t)m * DIMS);
    #pragma unroll
    for (int i = 0; i < 3; i++) dst[tid + i * 256] = src[tid + i * 256];

    if (tid == 0) {
        out[BROWS * NCLS + BROWS * DIMS + m] = sqrtf(d2e);     // l2s
        // classes dtype detection: int64 little-endian => odd int32 words all zero
        const unsigned* ci = (const unsigned*)cls;
        int nz = 0;
        for (int j = 1; j < 256; j += 2) nz += (ci[j] != 0u) ? 1 : 0;
        int cv;
        if (nz == 0) cv = (int)((const long long*)cls)[bidx];
        else         cv = ((const int*)cls)[bidx];
        #pragma unroll
        for (int j = 0; j < NCLS; j++) out[m * NCLS + j] = (j == cv) ? 1.0f : 0.0f;
    }
}

// ---------------- launcher ----------------
extern "C" void kernel_launch(void* const* d_in, const int* in_sizes, int n_in,
                              void* d_out, int out_size) {
    (void)in_sizes; (void)n_in; (void)out_size;
    const float* x       = (const float*)d_in[0];
    const float* samples = (const float*)d_in[1];
    const void*  cls     = d_in[2];
    float*       out     = (float*)d_out;

    void* p_best = nullptr;
    void* p_x2   = nullptr;
    cudaGetSymbolAddress(&p_best, g_best);
    cudaGetSymbolAddress(&p_x2, g_x2);
    cudaMemsetAsync(p_best, 0xFF, BROWS * sizeof(unsigned long long));
    cudaMemsetAsync(p_x2, 0, BROWS * sizeof(float));

    cudaFuncSetAttribute(pass1_kernel, cudaFuncAttributeMaxDynamicSharedMemorySize, 66560);
    prep_kernel<<<BROWS * 3, 256>>>(x);
    pass1_kernel<<<NGRID, NTHREADS, 66560>>>(samples);
    pass2_kernel<<<BROWS, 256>>>(x, samples, cls, out);
}

// round 15
// speedup vs baseline: 2.7427x; 1.2603x over previous
#include <cuda_runtime.h>
#include <cuda_bf16.h>
#include <cstdint>
#include <cfloat>

#define NSAMP   50000
#define DIMS    3072
#define BROWS   128
#define NCLS    10
#define KC      64            // K elements per smem chunk (64 bf16 = 128B = SW128 row)
#define NKC     48            // 3072 / 64
#define NT4TILES 296          // 296 tiles of N=128 -> 2 perfect waves
#define NT4BASE  37888        // 296*128
#define NT3TILES 127          // ceil((50000-37888)/96) tail tiles of N=96
#define DSTRIDE 50080         // row stride of d2 matrix (>= 37888+127*96 = 50080)
#define MARGIN  8.0f          // >5x worst-case bf16 d2 error bound
#define NTHREADS 384          // 256 consumer + 128 producer

// ---------------- device scratch (static globals; no allocation) ----------------
__device__ float g_x2[BROWS];
__device__ __align__(16) __nv_bfloat16 g_xb[NKC * 8192];      // X bf16, SW128-swizzled 16KB chunks
__device__ float g_d2[(size_t)BROWS * DSTRIDE];               // approx d2, 25.6 MB

// ---------------- helpers ----------------
__device__ __forceinline__ unsigned smem_u32(const void* p) {
    unsigned a;
    asm("{ .reg .u64 t; cvta.to.shared.u64 t, %1; cvt.u32.u64 %0, t; }" : "=r"(a) : "l"(p));
    return a;
}
__device__ __forceinline__ unsigned sw128(unsigned off) { return off ^ ((off >> 3) & 0x70); }
__device__ __forceinline__ unsigned long long umin64(unsigned long long a, unsigned long long b) {
    return a < b ? a : b;
}

__device__ __forceinline__ void ldsm_x4(unsigned r[4], unsigned addr) {
    asm volatile("ldmatrix.sync.aligned.m8n8.x4.shared.b16 {%0,%1,%2,%3}, [%4];"
                 : "=r"(r[0]), "=r"(r[1]), "=r"(r[2]), "=r"(r[3]) : "r"(addr));
}
__device__ __forceinline__ void ldsm_x2(unsigned r[2], unsigned addr) {
    asm volatile("ldmatrix.sync.aligned.m8n8.x2.shared.b16 {%0,%1}, [%2];"
                 : "=r"(r[0]), "=r"(r[1]) : "r"(addr));
}
__device__ __forceinline__ void mma_bf16(float c[4], const unsigned a[4], const unsigned b[2]) {
    asm volatile(
        "mma.sync.aligned.m16n8k16.row.col.f32.bf16.bf16.f32 "
        "{%0,%1,%2,%3}, {%4,%5,%6,%7}, {%8,%9}, {%0,%1,%2,%3};"
        : "+f"(c[0]), "+f"(c[1]), "+f"(c[2]), "+f"(c[3])
        : "r"(a[0]), "r"(a[1]), "r"(a[2]), "r"(a[3]), "r"(b[0]), "r"(b[1]));
}
__device__ __forceinline__ unsigned pack_bf16x2(float hi, float lo) {
    unsigned r;
    asm("cvt.rn.bf16x2.f32 %0, %1, %2;" : "=r"(r) : "f"(hi), "f"(lo));
    return r;
}
__device__ __forceinline__ void cp_async16(unsigned saddr, const void* gptr) {
    asm volatile("cp.async.ca.shared.global [%0], [%1], 16;" :: "r"(saddr), "l"(gptr) : "memory");
}
__device__ __forceinline__ void cp_async_wait_all() {
    asm volatile("cp.async.wait_all;" ::: "memory");
}
__device__ __forceinline__ void bar_sync(int id) {
    asm volatile("bar.sync %0, %1;" :: "r"(id), "r"(NTHREADS) : "memory");
}
__device__ __forceinline__ void bar_arrive(int id) {
    asm volatile("bar.arrive %0, %1;" :: "r"(id), "r"(NTHREADS) : "memory");
}

// ---------------- kernel 1: X -> bf16 swizzled chunks + ||x||^2 ----------------
// 384 blocks: 3 per row, 1024 elems each. g_x2 pre-zeroed by memset.
__global__ void __launch_bounds__(256) prep_kernel(const float* __restrict__ x) {
    const int b = blockIdx.x, tid = threadIdx.x;
    const int m = b / 3, seg = b % 3;
    float acc = 0.f;
    #pragma unroll
    for (int i = 0; i < 4; i++) {
        int k = seg * 1024 + tid + i * 256;
        float v = x[m * DIMS + k];
        acc += v * v;
        int kc = k >> 6, col = k & 63;
        unsigned sw = sw128((unsigned)(m * 128 + col * 2)) >> 1;   // element index
        g_xb[kc * 8192 + sw] = __float2bfloat16(v);
    }
    #pragma unroll
    for (int o = 16; o; o >>= 1) acc += __shfl_down_sync(0xffffffffu, acc, o);
    __shared__ float part[8];
    if ((tid & 31) == 0) part[tid >> 5] = acc;
    __syncthreads();
    if (tid == 0) {
        float t = 0.f;
        #pragma unroll
        for (int i = 0; i < 8; i++) t += part[i];
        atomicAdd(&g_x2[m], t);
    }
}

// ---------------- pass1 body: warp-specialized bf16 distance GEMM (R10 structure) ------
// NT = n8 subtiles per consumer warp (4 -> tile N=128, 3 -> tile N=96).
// Warps 0-7: consumers (ldsm + HMMA + d2 epilogue). Warps 8-11: producers
// (LDG fp32 -> bf16 -> STS, cp.async A chunk, exact s2).
template <int NT>
__device__ __forceinline__ void pass1_body(const float* __restrict__ samples, int n0) {
    extern __shared__ __align__(16) unsigned char dynsm[];
    __shared__ float s2[128];

    const int tid = threadIdx.x, lane = tid & 31, wid = tid >> 5;

    const unsigned dynbase = smem_u32(dynsm);
    const unsigned pad = ((dynbase + 1023u) & ~1023u) - dynbase;
    unsigned char* pA = dynsm + pad;                     // A bufs: pA + p*16384
    unsigned char* pB = pA + 32768;                      // B bufs: pB + p*16384
    const unsigned aA = dynbase + pad;
    const unsigned aB = aA + 32768;

    if (wid < 8) {
        // ================= CONSUMERS =================
        const int wm = wid >> 2, wn = wid & 3;           // warp tile: 64(M) x NT*8(N)
        const int a_row  = (lane & 7) + ((lane >> 3) & 1) * 8;
        const int a_koff = (lane >> 4) * 8;
        const int b_row  = (lane & 7);
        const int b_koff = (((lane & 15) >> 3)) * 8;

        float c[4][NT][4];
        #pragma unroll
        for (int mt = 0; mt < 4; mt++)
            #pragma unroll
            for (int nt = 0; nt < NT; nt++)
                #pragma unroll
                for (int r = 0; r < 4; r++) c[mt][nt][r] = 0.f;

        for (int kc = 0; kc < NKC; kc++) {
            const int p = kc & 1;
            bar_sync(4 + p);                             // wait FULL[p]
            const unsigned bA = aA + p * 16384, bB = aB + p * 16384;
            #pragma unroll
            for (int ks = 0; ks < 4; ks++) {
                unsigned a[4][4], b[NT][2];
                #pragma unroll
                for (int mt = 0; mt < 4; mt++) {
                    int row = wm * 64 + mt * 16 + a_row;
                    int ke  = ks * 16 + a_koff;
                    ldsm_x4(a[mt], bA + sw128((unsigned)(row * 128 + ke * 2)));
                }
                #pragma unroll
                for (int nt = 0; nt < NT; nt++) {
                    int row = wn * (NT * 8) + nt * 8 + b_row;
                    int ke  = ks * 16 + b_koff;
                    ldsm_x2(b[nt], bB + sw128((unsigned)(row * 128 + ke * 2)));
                }
                #pragma unroll
                for (int mt = 0; mt < 4; mt++)
                    #pragma unroll
                    for (int nt = 0; nt < NT; nt++)
                        mma_bf16(c[mt][nt], a[mt], b[nt]);
            }
            bar_arrive(2 + p);                           // signal EMPTY[p]
        }

        __syncthreads();                                 // producers published s2

        // epilogue: d2 = x2 + s2 - 2*dot, float2-coalesced (no fused min -> low reg pressure)
        const int g = lane >> 2, cq = lane & 3;
        #pragma unroll
        for (int mt = 0; mt < 4; mt++) {
            int r0 = wm * 64 + mt * 16 + g;
            float x2a = g_x2[r0], x2b = g_x2[r0 + 8];
            #pragma unroll
            for (int nt = 0; nt < NT; nt++) {
                int col = wn * (NT * 8) + nt * 8 + 2 * cq;
                int ng = n0 + col;
                float s2a = s2[col], s2b = s2[col + 1];
                float2 v0, v1;
                v0.x = fmaxf(x2a + s2a - 2.f * c[mt][nt][0], 0.f);
                v0.y = fmaxf(x2a + s2b - 2.f * c[mt][nt][1], 0.f);
                v1.x = fmaxf(x2b + s2a - 2.f * c[mt][nt][2], 0.f);
                v1.y = fmaxf(x2b + s2b - 2.f * c[mt][nt][3], 0.f);
                *(float2*)&g_d2[(size_t)r0 * DSTRIDE + ng] = v0;
                *(float2*)&g_d2[(size_t)(r0 + 8) * DSTRIDE + ng] = v1;
            }
        }
    } else {
        // ================= PRODUCERS =================
        const int ptid = tid - 256;                      // 0..127
        const int q = ptid & 15, rbase = ptid >> 4;      // col-quarter, row base
        const float* tb = samples + (size_t)(n0 + rbase) * DIMS + q * 4;

        float s2p[4 * NT];
        #pragma unroll
        for (int j = 0; j < 4 * NT; j++) s2p[j] = 0.f;

        float4 vb[4 * NT];

        for (int kc = 0; kc < NKC; kc++) {
            const int p = kc & 1;
            const int kb = kc * KC;

            // issue B loads BEFORE waiting: DRAM latency hides under consumer MMA
            #pragma unroll
            for (int j = 0; j < 4 * NT; j++) {
                int n = n0 + rbase + 8 * j;
                vb[j] = (n < NSAMP) ? *(const float4*)(tb + (size_t)(8 * j) * DIMS + kb)
                                    : make_float4(0.f, 0.f, 0.f, 0.f);
            }

            if (kc >= 2) bar_sync(2 + p);                // wait EMPTY[p]

            // A chunk via cp.async (L2-hot)
            {
                unsigned dstA = aA + p * 16384 + ptid * 16;
                const unsigned char* srcA = (const unsigned char*)g_xb + kc * 16384 + ptid * 16;
                #pragma unroll
                for (int i = 0; i < 8; i++)
                    cp_async16(dstA + i * 2048, srcA + i * 2048);
            }

            // convert B to bf16 + swizzled STS, accumulate exact s2
            unsigned char* dB = pB + p * 16384;
            #pragma unroll
            for (int j = 0; j < 4 * NT; j++) {
                float4 v = vb[j];
                s2p[j] = fmaf(v.x, v.x, fmaf(v.y, v.y, fmaf(v.z, v.z, fmaf(v.w, v.w, s2p[j]))));
                uint2 H;
                H.x = pack_bf16x2(v.y, v.x);
                H.y = pack_bf16x2(v.w, v.z);
                *(uint2*)(dB + sw128((unsigned)((rbase + 8 * j) * 128 + q * 8))) = H;
            }

            cp_async_wait_all();
            __threadfence_block();
            bar_arrive(4 + p);                           // signal FULL[p]
        }

        // s2 reduction: 16 threads (same rbase) share each row
        #pragma unroll
        for (int j = 0; j < 4 * NT; j++) {
            float v = s2p[j];
            #pragma unroll
            for (int o = 8; o; o >>= 1) v += __shfl_down_sync(0xffffffffu, v, o, 16);
            if ((lane & 15) == 0) s2[rbase + 8 * j] = v;
        }
        __syncthreads();                                 // matches consumers'
    }
}

// Separate entry points: independent register allocation per tile shape.
__global__ void __launch_bounds__(NTHREADS) pass1_nt4(const float* __restrict__ samples) {
    pass1_body<4>(samples, blockIdx.x * 128);
}
__global__ void __launch_bounds__(NTHREADS) pass1_nt3(const float* __restrict__ samples) {
    pass1_body<3>(samples, NT4BASE + blockIdx.x * 96);
}

// ---------------- kernel 3: per-row min + candidate exact rescore + outputs ----------------
__global__ void __launch_bounds__(256) pass2_kernel(const float* __restrict__ x,
                                                    const float* __restrict__ samples,
                                                    const void* __restrict__ cls,
                                                    float* __restrict__ out) {
    __shared__ unsigned long long wred[8];
    __shared__ unsigned long long s_best;
    __shared__ float fred[8];
    __shared__ int s_cand[2048];
    __shared__ int s_cnt;

    const int m = blockIdx.x, tid = threadIdx.x, lane = tid & 31, wid = tid >> 5;
    const float* drow = &g_d2[(size_t)m * DSTRIDE];

    // 1) approx min with packed (d2,idx) key -> jnp argmin tie-break (smallest idx)
    unsigned long long best = ~0ull;
    for (int i = tid; i < NSAMP; i += 256) {
        float d = drow[i];
        best = umin64(best, ((unsigned long long)__float_as_uint(d) << 32) | (unsigned)i);
    }
    #pragma unroll
    for (int o = 16; o; o >>= 1) best = umin64(best, __shfl_down_sync(0xffffffffu, best, o));
    if (lane == 0) wred[wid] = best;
    if (tid == 0) s_cnt = 0;
    __syncthreads();
    if (tid == 0) {
        unsigned long long b = wred[0];
        #pragma unroll
        for (int i = 1; i < 8; i++) b = umin64(b, wred[i]);
        s_best = b;
    }
    __syncthreads();

    // 2) collect candidates within margin of approx min
    const float thresh = __uint_as_float((unsigned)(s_best >> 32)) + MARGIN;
    for (int i = tid; i < NSAMP; i += 256) {
        if (drow[i] <= thresh) {
            int p = atomicAdd(&s_cnt, 1);
            if (p < 2048) s_cand[p] = i;
        }
    }
    __syncthreads();
    const int cnt = s_cnt < 2048 ? s_cnt : 2048;

    // 3) exact fp32 rescore of candidates
    unsigned long long ebest = ~0ull;   // only thread 0's value is meaningful
    const float* xr = x + (size_t)m * DIMS;
    for (int ci = 0; ci < cnt; ci++) {
        int idx = s_cand[ci];
        const float* sr = samples + (size_t)idx * DIMS;
        float acc = 0.f;
        for (int j = tid; j < DIMS; j += 256) {
            float dx = xr[j] - sr[j];
            acc = fmaf(dx, dx, acc);
        }
        #pragma unroll
        for (int o = 16; o; o >>= 1) acc += __shfl_down_sync(0xffffffffu, acc, o);
        if (lane == 0) fred[wid] = acc;
        __syncthreads();
        if (tid == 0) {
            float t = 0.f;
            #pragma unroll
            for (int i = 0; i < 8; i++) t += fred[i];
            ebest = umin64(ebest, ((unsigned long long)__float_as_uint(fmaxf(t, 0.f)) << 32)
                                  | (unsigned)idx);
        }
        __syncthreads();
    }
    if (tid == 0) s_best = ebest;
    __syncthreads();

    const unsigned bidx = (unsigned)(s_best & 0xffffffffu);
    const float d2e = __uint_as_float((unsigned)(s_best >> 32));

    // imgs: out[1280 .. 1280 + 128*3072)
    const float4* src = (const float4*)(samples + (size_t)bidx * DIMS);
    float4* dst = (float4*)(out + BROWS * NCLS + (size_t)m * DIMS);
    #pragma unroll
    for (int i = 0; i < 3; i++) dst[tid + i * 256] = src[tid + i * 256];

    if (tid == 0) {
        out[BROWS * NCLS + BROWS * DIMS + m] = sqrtf(d2e);     // l2s
        // classes dtype detection: int64 little-endian => odd int32 words all zero
        const unsigned* ci = (const unsigned*)cls;
        int nz = 0;
        for (int j = 1; j < 256; j += 2) nz += (ci[j] != 0u) ? 1 : 0;
        int cv;
        if (nz == 0) cv = (int)((const long long*)cls)[bidx];
        else         cv = ((const int*)cls)[bidx];
        #pragma unroll
        for (int j = 0; j < NCLS; j++) out[m * NCLS + j] = (j == cv) ? 1.0f : 0.0f;
    }
}

// ---------------- launcher ----------------
extern "C" void kernel_launch(void* const* d_in, const int* in_sizes, int n_in,
                              void* d_out, int out_size) {
    (void)in_sizes; (void)n_in; (void)out_size;
    const float* x       = (const float*)d_in[0];
    const float* samples = (const float*)d_in[1];
    const void*  cls     = d_in[2];
    float*       out     = (float*)d_out;

    void* p_x2 = nullptr;
    cudaGetSymbolAddress(&p_x2, g_x2);
    cudaMemsetAsync(p_x2, 0, BROWS * sizeof(float));

    cudaFuncSetAttribute(pass1_nt4, cudaFuncAttributeMaxDynamicSharedMemorySize, 66560);
    cudaFuncSetAttribute(pass1_nt3, cudaFuncAttributeMaxDynamicSharedMemorySize, 66560);
    prep_kernel<<<BROWS * 3, 256>>>(x);
    pass1_nt4<<<NT4TILES, NTHREADS, 66560>>>(samples);
    pass1_nt3<<<NT3TILES, NTHREADS, 66560>>>(samples);
    pass2_kernel<<<BROWS, 256>>>(x, samples, cls, out);
}